// round 16
// baseline (speedup 1.0000x reference)
#include <cuda_runtime.h>
#include <cuda_bf16.h>
#include <math.h>

#define NN 50000
#define NE 800000
#define HD 256
#define NG 64
#define SCAN_BLKS 196   // ceil(50000/256)

// ---------------- scratch (device globals; no runtime allocation) ----------------
__device__ __align__(16) float g_h [(size_t)NN*HD];
__device__ __align__(16) float g_r [(size_t)NN*HD];
__device__ __align__(16) float g_xp[(size_t)NN*HD];
__device__ float g_dinv[NN];
__device__ int   g_cnt[NN];
__device__ int   g_incl[NN];
__device__ int   g_rowptr[NN+1];
__device__ int   g_cursor[NN];
__device__ __align__(16) int2 g_edge[NE];
__device__ int   g_bsum[SCAN_BLKS];
__device__ int   g_bscan[SCAN_BLKS];
__device__ __align__(16) float g_stat0[HD];      // input BN stats
__device__ __align__(16) float g_stat1[HD];
__device__ __align__(16) float g_ls0[3*HD];      // per-layer hidden BN stats
__device__ __align__(16) float g_ls1[3*HD];
// pre-packed bf16x2 weights TRANSPOSED: [N][K/2] u32; hi and mid parts
__device__ __align__(16) unsigned g_W0h[HD*HD/2], g_W0m[HD*HD/2];
__device__ __align__(16) unsigned g_W1h[HD*HD/2], g_W1m[HD*HD/2];
__device__ __align__(16) unsigned g_W2h[HD*HD/2], g_W2m[HD*HD/2];
__device__ __align__(16) unsigned g_Wa1h[128*HD/2], g_Wa1m[128*HD/2];
__device__ __align__(16) float g_cb[HD];
__device__ float g_score[NN];
__device__ float g_pm[SCAN_BLKS], g_ps[SCAN_BLKS];
__device__ float g_soft[2];
__device__ __align__(16) float g_pooled[NG*HD];
__device__ float g_cntf[NG];

// ---------------- helpers ----------------
__device__ __forceinline__ unsigned pack_bf16(float lo, float hi) {
    unsigned r;
    asm("cvt.rn.bf16x2.f32 %0, %1, %2;" : "=r"(r) : "f"(hi), "f"(lo));
    return r;
}
__device__ __forceinline__ float bf16rt(float x) {
    __nv_bfloat16 b = __float2bfloat16_rn(x);
    return __bfloat162float(b);
}
__device__ __forceinline__ void mma_bf16(float* c,
    unsigned a0, unsigned a1, unsigned a2, unsigned a3,
    unsigned b0, unsigned b1)
{
    asm volatile(
        "mma.sync.aligned.m16n8k16.row.col.f32.bf16.bf16.f32 "
        "{%0,%1,%2,%3},{%4,%5,%6,%7},{%8,%9},{%0,%1,%2,%3};\n"
        : "+f"(c[0]), "+f"(c[1]), "+f"(c[2]), "+f"(c[3])
        : "r"(a0), "r"(a1), "r"(a2), "r"(a3), "r"(b0), "r"(b1));
}
__device__ __forceinline__ void ldsm4(unsigned* r, const void* p) {
    unsigned a = (unsigned)__cvta_generic_to_shared(p);
    asm volatile("ldmatrix.sync.aligned.m8n8.x4.shared.b16 {%0,%1,%2,%3}, [%4];"
        : "=r"(r[0]), "=r"(r[1]), "=r"(r[2]), "=r"(r[3]) : "r"(a));
}
__device__ __forceinline__ unsigned sw128(unsigned b) { return b ^ ((b >> 3) & 0x70u); }
__device__ __forceinline__ void cpa16(unsigned dst, const void* src) {
    asm volatile("cp.async.cg.shared.global [%0], [%1], 16;"
        :: "r"(dst), "l"(src) : "memory");
}

// ---------------- input BN stats ----------------
__global__ void colstats_x(const float* __restrict__ x) {
    int t = threadIdx.x;
    float s = 0.f, q = 0.f;
    for (int r = blockIdx.x; r < NN; r += gridDim.x) {
        float v = x[(size_t)r*HD + t];
        s += v; q += v*v;
    }
    atomicAdd(&g_stat0[t], s);
    atomicAdd(&g_stat1[t], q);
}

// Fold input BN into W0 (transposed packed bf16x2 hi/mid) + folded bias cb.
__global__ void fold0(const float* __restrict__ W0, const float* __restrict__ bing,
                      const float* __restrict__ binb) {
    int j = threadIdx.x;
    int k2 = blockIdx.x;
    if (k2 < HD/2) {
        int k0 = 2*k2, k1 = 2*k2+1;
        float m0 = g_stat0[k0]*(1.f/NN), m1 = g_stat0[k1]*(1.f/NN);
        float a0 = rsqrtf(g_stat1[k0]*(1.f/NN) - m0*m0 + 1e-5f) * bing[k0];
        float a1 = rsqrtf(g_stat1[k1]*(1.f/NN) - m1*m1 + 1e-5f) * bing[k1];
        float v0 = a0 * W0[k0*HD + j];
        float v1 = a1 * W0[k1*HD + j];
        float h0 = bf16rt(v0), h1 = bf16rt(v1);
        g_W0h[j*(HD/2) + k2] = pack_bf16(h0, h1);
        g_W0m[j*(HD/2) + k2] = pack_bf16(v0 - h0, v1 - h1);
    } else {
        __shared__ float scin[HD];
        float m = g_stat0[j]*(1.f/NN);
        float rs = rsqrtf(g_stat1[j]*(1.f/NN) - m*m + 1e-5f);
        scin[j] = binb[j] - m * rs * bing[j];
        __syncthreads();
        float s = 0.f;
        for (int kk = 0; kk < HD; kk++) s += scin[kk] * W0[kk*HD + j];
        g_cb[j] = s;
    }
}

// all three remaining weights -> transposed packed bf16x2 hi/mid, one launch
__global__ void presplit_all(const float* __restrict__ W1, const float* __restrict__ W2,
                             const float* __restrict__ Wa1) {
    int idx = blockIdx.x*256 + threadIdx.x;
    const float* src; unsigned *dh, *dm; int Nn, local;
    if (idx < 32768)      { src = W1;  dh = g_W1h;  dm = g_W1m;  Nn = 256; local = idx; }
    else if (idx < 65536) { src = W2;  dh = g_W2h;  dm = g_W2m;  Nn = 256; local = idx - 32768; }
    else if (idx < 81920) { src = Wa1; dh = g_Wa1h; dm = g_Wa1m; Nn = 128; local = idx - 65536; }
    else return;
    int n = local >> 7, k2 = local & 127;
    float v0 = src[(2*k2)*Nn + n];
    float v1 = src[(2*k2+1)*Nn + n];
    float h0 = bf16rt(v0), h1 = bf16rt(v1);
    dh[local] = pack_bf16(h0, h1);
    dm[local] = pack_bf16(v0 - h0, v1 - h1);
}

// ---------------- degree / CSR build ----------------
__global__ void deg_kernel(const int* __restrict__ dst) {
    for (int e = blockIdx.x*blockDim.x + threadIdx.x; e < NE; e += gridDim.x*blockDim.x)
        atomicAdd(&g_cnt[dst[e]], 1);
}
__global__ void scan1() {
    __shared__ int sm[256];
    int t = threadIdx.x;
    int i = blockIdx.x*256 + t;
    int v = (i < NN) ? g_cnt[i] : 0;
    if (i < NN) g_dinv[i] = rsqrtf((float)v + 1.f);
    sm[t] = v; __syncthreads();
    for (int off = 1; off < 256; off <<= 1) {
        int tv = (t >= off) ? sm[t-off] : 0;
        __syncthreads();
        sm[t] += tv;
        __syncthreads();
    }
    if (i < NN) g_incl[i] = sm[t];
    if (t == 255) g_bsum[blockIdx.x] = sm[255];
}
__global__ void scan2() {
    __shared__ int sm[256];
    int t = threadIdx.x;
    sm[t] = (t < SCAN_BLKS) ? g_bsum[t] : 0; __syncthreads();
    for (int off = 1; off < 256; off <<= 1) {
        int tv = (t >= off) ? sm[t-off] : 0;
        __syncthreads();
        sm[t] += tv;
        __syncthreads();
    }
    if (t < SCAN_BLKS) g_bscan[t] = sm[t];
}
__global__ void scan3() {
    int t = threadIdx.x;
    int i = blockIdx.x*256 + t;
    if (i < NN) {
        int off = (blockIdx.x > 0) ? g_bscan[blockIdx.x-1] : 0;
        int ex = off + g_incl[i] - g_cnt[i];
        g_rowptr[i] = ex;
        g_cursor[i] = ex;
        g_cnt[i] = 0;
    }
    if (i == 0) g_rowptr[NN] = NE;
}
__global__ void fill_kernel(const int* __restrict__ src, const int* __restrict__ dst) {
    for (int e = blockIdx.x*blockDim.x + threadIdx.x; e < NE; e += gridDim.x*blockDim.x) {
        int d = dst[e];
        int s = src[e];
        int p = atomicAdd(&g_cursor[d], 1);
        float cf = g_dinv[s] * g_dinv[d];
        g_edge[p] = make_int2(s, __float_as_int(cf));
    }
}

// ---------------- 3xBF16 tensor-core GEMM (ldmatrix + SW128 + cp.async B) ----------------
// MMA issued in 3 passes (hh, mh, hm over all 16 warp-subtiles) so dependent MMAs on the
// same accumulator are separated by 15 independent ones. Per-acc accumulation order is
// unchanged (hh then mh then hm) -> bitwise-identical results.
__global__ __launch_bounds__(256, 2) void bf16_gemm(
    const float* __restrict__ A, const unsigned* __restrict__ Bth,
    const unsigned* __restrict__ Btm,
    const float* __restrict__ bias, float* __restrict__ C, int M, int Nn,
    const float* __restrict__ Wa2, const float* __restrict__ ba2,
    float* __restrict__ score)
{
    __shared__ __align__(16) unsigned char smAh[2][4096], smAm[2][4096];
    __shared__ __align__(16) unsigned char smBh[2][4096], smBm[2][4096];
    __shared__ float srow[128];

    int tid = threadIdx.x;
    int bm = blockIdx.x*128, bn = blockIdx.y*128;
    int lane = tid & 31, w = tid >> 5;
    int wm = (w >> 2) * 64, wn = (w & 3) * 32;
    int lr = lane & 15, lh = lane >> 4;
    int lrow = lane >> 2, tg = lane & 3;

    int arow = tid & 127, aks = tid >> 7;
    int brow = tid >> 1,  bks = tid & 1;

    unsigned asw = sw128((unsigned)(arow*32 + aks*16));
    unsigned bsw = sw128((unsigned)(brow*32 + bks*16));
    unsigned sbh0 = (unsigned)__cvta_generic_to_shared(&smBh[0][0]);
    unsigned sbm0 = (unsigned)__cvta_generic_to_shared(&smBm[0][0]);
    const char* bSrcH = (const char*)Bth + ((size_t)(bn+brow)*128 + bks*4) * 4;
    const char* bSrcM = (const char*)Btm + ((size_t)(bn+brow)*128 + bks*4) * 4;

    float4 ra0, ra1;

    float acc[4][4][4];
    #pragma unroll
    for (int a = 0; a < 4; a++)
        #pragma unroll
        for (int b = 0; b < 4; b++)
            #pragma unroll
            for (int cc = 0; cc < 4; cc++) acc[a][b][cc] = 0.f;

    auto LOADA = [&](int kt) {
        const float* ap = A + (size_t)(bm+arow)*256 + kt*16 + aks*8;
        if (bm + arow < M) { ra0 = *(const float4*)ap; ra1 = *(const float4*)(ap+4); }
        else { ra0 = make_float4(0.f,0.f,0.f,0.f); ra1 = ra0; }
    };
    auto CPB = [&](int kt, int buf) {
        size_t ko = (size_t)kt*32;
        cpa16(sbh0 + buf*4096 + bsw, bSrcH + ko);
        cpa16(sbm0 + buf*4096 + bsw, bSrcM + ko);
        asm volatile("cp.async.commit_group;" ::: "memory");
    };
    auto STOREA = [&](int buf) {
        float v[8] = {ra0.x, ra0.y, ra0.z, ra0.w, ra1.x, ra1.y, ra1.z, ra1.w};
        unsigned hp[4], mp[4];
        #pragma unroll
        for (int j = 0; j < 4; j++) {
            float e = v[2*j], o = v[2*j+1];
            float eh = bf16rt(e), oh = bf16rt(o);
            hp[j] = pack_bf16(eh, oh);
            mp[j] = pack_bf16(e - eh, o - oh);
        }
        *(uint4*)&smAh[buf][asw] = make_uint4(hp[0], hp[1], hp[2], hp[3]);
        *(uint4*)&smAm[buf][asw] = make_uint4(mp[0], mp[1], mp[2], mp[3]);
    };

    if (score && tid < 128) srow[tid] = 0.f;

    LOADA(0); CPB(0, 0); STOREA(0);
    asm volatile("cp.async.wait_group 0;" ::: "memory");
    __syncthreads();

    for (int kt = 0; kt < 16; kt++) {
        int buf = kt & 1;
        if (kt < 15) { LOADA(kt+1); CPB(kt+1, buf ^ 1); }

        unsigned ah[4][4], am[4][4], bh[2][4], bmm[2][4];
        #pragma unroll
        for (int mt = 0; mt < 4; mt++) {
            unsigned byte = sw128((unsigned)((wm + mt*16 + lr)*32 + lh*16));
            ldsm4(ah[mt], &smAh[buf][byte]);
            ldsm4(am[mt], &smAm[buf][byte]);
        }
        #pragma unroll
        for (int np = 0; np < 2; np++) {
            unsigned byte = sw128((unsigned)((wn + np*16 + lr)*32 + lh*16));
            ldsm4(bh[np],  &smBh[buf][byte]);
            ldsm4(bmm[np], &smBm[buf][byte]);
        }
        // pass 1: Ah x Bh on all 16 subtiles
        #pragma unroll
        for (int nt = 0; nt < 4; nt++) {
            int np = nt >> 1, sel = nt & 1;
            unsigned b0 = bh[np][sel], b1 = bh[np][sel+2];
            #pragma unroll
            for (int mt = 0; mt < 4; mt++)
                mma_bf16(acc[mt][nt], ah[mt][0],ah[mt][1],ah[mt][2],ah[mt][3], b0, b1);
        }
        // pass 2: Am x Bh
        #pragma unroll
        for (int nt = 0; nt < 4; nt++) {
            int np = nt >> 1, sel = nt & 1;
            unsigned b0 = bh[np][sel], b1 = bh[np][sel+2];
            #pragma unroll
            for (int mt = 0; mt < 4; mt++)
                mma_bf16(acc[mt][nt], am[mt][0],am[mt][1],am[mt][2],am[mt][3], b0, b1);
        }
        // pass 3: Ah x Bm
        #pragma unroll
        for (int nt = 0; nt < 4; nt++) {
            int np = nt >> 1, sel = nt & 1;
            unsigned b0 = bmm[np][sel], b1 = bmm[np][sel+2];
            #pragma unroll
            for (int mt = 0; mt < 4; mt++)
                mma_bf16(acc[mt][nt], ah[mt][0],ah[mt][1],ah[mt][2],ah[mt][3], b0, b1);
        }
        if (kt < 15) {
            STOREA(buf ^ 1);
            asm volatile("cp.async.wait_group 0;" ::: "memory");
            __syncthreads();
        }
    }

    if (score) {
        __syncthreads();
        #pragma unroll
        for (int mt = 0; mt < 4; mt++) {
            float p0 = 0.f, p1 = 0.f;
            #pragma unroll
            for (int nt = 0; nt < 4; nt++) {
                int cidx = wn + nt*8 + 2*tg;
                float bv0 = bias[cidx], bv1 = bias[cidx+1];
                float w0 = Wa2[cidx],  w1 = Wa2[cidx+1];
                float v;
                v = acc[mt][nt][0] + bv0; v = (v > 0.f) ? v : 0.01f*v; p0 = fmaf(v, w0, p0);
                v = acc[mt][nt][1] + bv1; v = (v > 0.f) ? v : 0.01f*v; p0 = fmaf(v, w1, p0);
                v = acc[mt][nt][2] + bv0; v = (v > 0.f) ? v : 0.01f*v; p1 = fmaf(v, w0, p1);
                v = acc[mt][nt][3] + bv1; v = (v > 0.f) ? v : 0.01f*v; p1 = fmaf(v, w1, p1);
            }
            int rl = wm + mt*16 + lrow;
            atomicAdd(&srow[rl],     p0);
            atomicAdd(&srow[rl + 8], p1);
        }
        __syncthreads();
        if (tid < 128 && bm + tid < M) score[bm + tid] = srow[tid] + ba2[0];
        return;
    }

    #pragma unroll
    for (int nt = 0; nt < 4; nt++) {
        int cidx = bn + wn + nt*8 + 2*tg;
        float b0v = bias ? bias[cidx]   : 0.f;
        float b1v = bias ? bias[cidx+1] : 0.f;
        #pragma unroll
        for (int mt = 0; mt < 4; mt++) {
            int r0 = bm + wm + mt*16 + lrow;
            if (r0 < M)
                *(float2*)(C + (size_t)r0*Nn + cidx) =
                    make_float2(acc[mt][nt][0]+b0v, acc[mt][nt][1]+b1v);
            if (r0 + 8 < M)
                *(float2*)(C + (size_t)(r0+8)*Nn + cidx) =
                    make_float2(acc[mt][nt][2]+b0v, acc[mt][nt][3]+b1v);
        }
    }
}

// ---------------- aggregation + bias + relu + per-layer BN-stat partials (R13-proven) ----
__global__ __launch_bounds__(256) void agg_kernel(const float* __restrict__ bias, int layer) {
    int c = (threadIdx.x & 127) * 2;
    int half = threadIdx.x >> 7;
    int row0 = blockIdx.x * 32 + half * 16;
    float2 bia = *(const float2*)&bias[c];
    float ssx=0.f, ssy=0.f, qqx=0.f, qqy=0.f;
    for (int r = 0; r < 16; r++) {
        int i = row0 + r;
        if (i >= NN) break;
        float di = g_dinv[i];
        float2 hv = *(const float2*)&g_h[(size_t)i*HD + c];
        float ax = hv.x * di * di, ay = hv.y * di * di;
        int p = g_rowptr[i], e = g_rowptr[i+1];
        for (; p + 8 <= e; p += 8) {
            int2 e0 = g_edge[p],   e1 = g_edge[p+1];
            int2 e2 = g_edge[p+2], e3 = g_edge[p+3];
            int2 e4 = g_edge[p+4], e5 = g_edge[p+5];
            int2 e6 = g_edge[p+6], e7 = g_edge[p+7];
            float2 v0 = *(const float2*)&g_h[(size_t)e0.x*HD + c];
            float2 v1 = *(const float2*)&g_h[(size_t)e1.x*HD + c];
            float2 v2 = *(const float2*)&g_h[(size_t)e2.x*HD + c];
            float2 v3 = *(const float2*)&g_h[(size_t)e3.x*HD + c];
            float2 v4 = *(const float2*)&g_h[(size_t)e4.x*HD + c];
            float2 v5 = *(const float2*)&g_h[(size_t)e5.x*HD + c];
            float2 v6 = *(const float2*)&g_h[(size_t)e6.x*HD + c];
            float2 v7 = *(const float2*)&g_h[(size_t)e7.x*HD + c];
            float f0 = __int_as_float(e0.y), f1 = __int_as_float(e1.y);
            float f2 = __int_as_float(e2.y), f3 = __int_as_float(e3.y);
            float f4 = __int_as_float(e4.y), f5 = __int_as_float(e5.y);
            float f6 = __int_as_float(e6.y), f7 = __int_as_float(e7.y);
            ax = fmaf(v0.x, f0, ax); ay = fmaf(v0.y, f0, ay);
            ax = fmaf(v1.x, f1, ax); ay = fmaf(v1.y, f1, ay);
            ax = fmaf(v2.x, f2, ax); ay = fmaf(v2.y, f2, ay);
            ax = fmaf(v3.x, f3, ax); ay = fmaf(v3.y, f3, ay);
            ax = fmaf(v4.x, f4, ax); ay = fmaf(v4.y, f4, ay);
            ax = fmaf(v5.x, f5, ax); ay = fmaf(v5.y, f5, ay);
            ax = fmaf(v6.x, f6, ax); ay = fmaf(v6.y, f6, ay);
            ax = fmaf(v7.x, f7, ax); ay = fmaf(v7.y, f7, ay);
        }
        for (; p < e; p++) {
            int2 ed = g_edge[p];
            float2 vv = *(const float2*)&g_h[(size_t)ed.x*HD + c];
            float ff = __int_as_float(ed.y);
            ax = fmaf(vv.x, ff, ax); ay = fmaf(vv.y, ff, ay);
        }
        float vx = fmaxf(ax + bia.x, 0.f);
        float vy = fmaxf(ay + bia.y, 0.f);
        *(float2*)&g_r[(size_t)i*HD + c] = make_float2(vx, vy);
        ssx += vx; ssy += vy; qqx += vx*vx; qqy += vy*vy;
    }
    atomicAdd(&g_ls0[layer*HD + c],   ssx);
    atomicAdd(&g_ls0[layer*HD + c+1], ssy);
    atomicAdd(&g_ls1[layer*HD + c],   qqx);
    atomicAdd(&g_ls1[layer*HD + c+1], qqy);
}

// xp = bn(r) (+ xp if residual); A/C computed per block from per-layer stats
__global__ void bnnorm_kernel(int residual, int layer,
                              const float* __restrict__ g, const float* __restrict__ b) {
    __shared__ float sA[HD], sC[HD];
    int t = threadIdx.x;
    {
        float m = g_ls0[layer*HD + t] * (1.f/NN);
        float v = g_ls1[layer*HD + t] * (1.f/NN) - m*m;
        float rs = rsqrtf(v + 1e-5f);
        sA[t] = rs * g[t];
        sC[t] = b[t] - m * rs * g[t];
    }
    __syncthreads();
    int idx = blockIdx.x*256 + t;
    if (idx >= NN*HD/4) return;
    int c4 = idx & 63;
    float4 v = ((const float4*)g_r)[idx];
    float4 A = *(const float4*)&sA[c4*4];
    float4 C = *(const float4*)&sC[c4*4];
    float4 o = make_float4(v.x*A.x+C.x, v.y*A.y+C.y, v.z*A.z+C.z, v.w*A.w+C.w);
    if (residual) {
        float4 p = ((const float4*)g_xp)[idx];
        o.x += p.x; o.y += p.y; o.z += p.z; o.w += p.w;
    }
    ((float4*)g_xp)[idx] = o;
}

// ---------------- softmax over all N (+ per-group count histogram) ----------------
__global__ void smax_part(const int* __restrict__ batch) {
    __shared__ float sm[256], ss[256];
    __shared__ int hist[NG];
    int t = threadIdx.x;
    if (t < NG) hist[t] = 0;
    float m = -3.4e38f, s = 0.f;
    for (int i = blockIdx.x*256 + t; i < NN; i += SCAN_BLKS*256) {
        float v = g_score[i];
        float nm = fmaxf(m, v);
        float ns = expf(v - nm);
        if (s > 0.f) ns += s * expf(m - nm);
        s = ns; m = nm;
        atomicAdd(&hist[batch[i]], 1);
    }
    sm[t] = m; ss[t] = s; __syncthreads();
    for (int off = 128; off; off >>= 1) {
        if (t < off) {
            float m2 = sm[t+off], s2 = ss[t+off];
            float nm = fmaxf(sm[t], m2);
            float acc = 0.f;
            if (ss[t] > 0.f) acc += ss[t] * expf(sm[t] - nm);
            if (s2    > 0.f) acc += s2    * expf(m2    - nm);
            sm[t] = nm; ss[t] = acc;
        }
        __syncthreads();
    }
    if (t == 0) { g_pm[blockIdx.x] = sm[0]; g_ps[blockIdx.x] = ss[0]; }
    if (t < NG && hist[t]) atomicAdd(&g_cntf[t], (float)hist[t]);
}
__global__ void smax_final() {
    __shared__ float sm[256], ss[256];
    int t = threadIdx.x;
    sm[t] = (t < SCAN_BLKS) ? g_pm[t] : -3.4e38f;
    ss[t] = (t < SCAN_BLKS) ? g_ps[t] : 0.f;
    __syncthreads();
    for (int off = 128; off; off >>= 1) {
        if (t < off) {
            float m2 = sm[t+off], s2 = ss[t+off];
            float nm = fmaxf(sm[t], m2);
            float acc = 0.f;
            if (ss[t] > 0.f) acc += ss[t] * expf(sm[t] - nm);
            if (s2    > 0.f) acc += s2    * expf(m2    - nm);
            sm[t] = nm; ss[t] = acc;
        }
        __syncthreads();
    }
    if (t == 0) { g_soft[0] = sm[0]; g_soft[1] = 1.f / ss[0]; }
}

// pooled[g] += sum xp[i]*w[i], w computed inline from score; float2 columns.
__global__ __launch_bounds__(256) void pool_kernel(const int* __restrict__ batch) {
    int c = (threadIdx.x & 127) * 2;
    int half = threadIdx.x >> 7;
    int row0 = blockIdx.x * 128 + half * 64;
    if (row0 >= NN) return;
    float smax = g_soft[0], sinv = g_soft[1];
    float ax = 0.f, ay = 0.f;
    int cur = batch[row0];
    for (int r = 0; r < 64; r++) {
        int i = row0 + r;
        if (i >= NN) break;
        int g = batch[i];
        if (g != cur) {
            if (ax != 0.f || ay != 0.f) {
                atomicAdd(&g_pooled[cur*HD + c],   ax);
                atomicAdd(&g_pooled[cur*HD + c+1], ay);
            }
            ax = 0.f; ay = 0.f; cur = g;
        }
        float wv = expf(g_score[i] - smax) * sinv;
        float2 v = *(const float2*)&g_xp[(size_t)i*HD + c];
        ax = fmaf(v.x, wv, ax);
        ay = fmaf(v.y, wv, ay);
    }
    atomicAdd(&g_pooled[cur*HD + c],   ax);
    atomicAdd(&g_pooled[cur*HD + c+1], ay);
}

// out + reset of all replay-accumulated state
__global__ void final_kernel(const float* __restrict__ Wo, const float* __restrict__ bo,
                             float* __restrict__ out) {
    int t = threadIdx.x;
    float s = 0.f;
    int g = t >> 1, o = t & 1;
    if (t < NG*2) {
        for (int h = 0; h < HD; h++) s = fmaf(g_pooled[g*HD + h], Wo[h*2 + o], s);
        s = s / fmaxf(g_cntf[g], 1.f) + bo[o];
    }
    __syncthreads();
    if (t < NG*2) out[t] = s;
    for (int i = t; i < NG*HD; i += 128) g_pooled[i] = 0.f;
    if (t < NG) g_cntf[t] = 0.f;
    for (int i = t; i < 3*HD; i += 128) { g_ls0[i] = 0.f; g_ls1[i] = 0.f; }
    for (int i = t; i < HD; i += 128) { g_stat0[i] = 0.f; g_stat1[i] = 0.f; }
}

// ---------------- launch ----------------
extern "C" void kernel_launch(void* const* d_in, const int* in_sizes, int n_in,
                              void* d_out, int out_size) {
    const float* x      = (const float*)d_in[0];
    const int*   ei     = (const int*)d_in[1];
    const int*   src    = ei;
    const int*   dst    = ei + NE;
    const int*   batch  = (const int*)d_in[2];
    const float* bing   = (const float*)d_in[3];
    const float* binb   = (const float*)d_in[4];
    const float* W[3]   = {(const float*)d_in[5],  (const float*)d_in[9],  (const float*)d_in[13]};
    const float* bL[3]  = {(const float*)d_in[6],  (const float*)d_in[10], (const float*)d_in[14]};
    const float* bng[3] = {(const float*)d_in[7],  (const float*)d_in[11], (const float*)d_in[15]};
    const float* bnb[3] = {(const float*)d_in[8],  (const float*)d_in[12], (const float*)d_in[16]};
    const float* Wa1    = (const float*)d_in[17];
    const float* ba1    = (const float*)d_in[18];
    const float* Wa2    = (const float*)d_in[19];
    const float* ba2    = (const float*)d_in[20];
    const float* Wo     = (const float*)d_in[21];
    const float* bo     = (const float*)d_in[22];
    float* out = (float*)d_out;

    void* p;
    cudaGetSymbolAddress(&p, g_h);     float* ph   = (float*)p;
    cudaGetSymbolAddress(&p, g_xp);    float* pxp  = (float*)p;
    cudaGetSymbolAddress(&p, g_score); float* psc  = (float*)p;
    cudaGetSymbolAddress(&p, g_W0h);  unsigned* pw0h = (unsigned*)p;
    cudaGetSymbolAddress(&p, g_W0m);  unsigned* pw0m = (unsigned*)p;
    cudaGetSymbolAddress(&p, g_W1h);  unsigned* pw1h = (unsigned*)p;
    cudaGetSymbolAddress(&p, g_W1m);  unsigned* pw1m = (unsigned*)p;
    cudaGetSymbolAddress(&p, g_W2h);  unsigned* pw2h = (unsigned*)p;
    cudaGetSymbolAddress(&p, g_W2m);  unsigned* pw2m = (unsigned*)p;
    cudaGetSymbolAddress(&p, g_Wa1h); unsigned* pwah = (unsigned*)p;
    cudaGetSymbolAddress(&p, g_Wa1m); unsigned* pwam = (unsigned*)p;
    cudaGetSymbolAddress(&p, g_cb);   float* pcb  = (float*)p;

    dim3 gemm_grid((NN+127)/128, 2);
    dim3 attn_grid((NN+127)/128, 1);
    int agg_blocks = (NN+31)/32;
    int bn_blocks = (NN*HD/4 + 255)/256;

    colstats_x<<<512,256>>>(x);
    fold0<<<HD/2+1,HD>>>(W[0], bing, binb);
    presplit_all<<<320,256>>>(W[1], W[2], Wa1);
    bf16_gemm<<<gemm_grid,256>>>(x, pw0h, pw0m, pcb, ph, NN, HD,
                                 nullptr, nullptr, nullptr);        // <- profiled (4th launch)

    // CSR build (independent of GEMM result)
    deg_kernel<<<1024,256>>>(dst);
    scan1<<<SCAN_BLKS,256>>>();
    scan2<<<1,256>>>();
    scan3<<<SCAN_BLKS,256>>>();
    fill_kernel<<<1024,256>>>(src, dst);

    // layer 0
    agg_kernel<<<agg_blocks,256>>>(bL[0], 0);
    bnnorm_kernel<<<bn_blocks,256>>>(0, 0, bng[0], bnb[0]);

    // layers 1,2 with residual
    unsigned* pwsh[3] = {pw0h, pw1h, pw2h};
    unsigned* pwsm[3] = {pw0m, pw1m, pw2m};
    for (int l = 1; l < 3; l++) {
        bf16_gemm<<<gemm_grid,256>>>(pxp, pwsh[l], pwsm[l], nullptr, ph, NN, HD,
                                     nullptr, nullptr, nullptr);
        agg_kernel<<<agg_blocks,256>>>(bL[l], l);
        bnnorm_kernel<<<bn_blocks,256>>>(1, l, bng[l], bnb[l]);
    }

    // attention: GEMM with fused lrelu·Wa2 score epilogue
    bf16_gemm<<<attn_grid,256>>>(pxp, pwah, pwam, ba1, nullptr, NN, 128,
                                 Wa2, ba2, psc);
    smax_part<<<SCAN_BLKS,256>>>(batch);
    smax_final<<<1,256>>>();
    pool_kernel<<<(NN+127)/128,256>>>(batch);
    final_kernel<<<1,128>>>(Wo, bo, out);
}

// round 17
// speedup vs baseline: 1.1111x; 1.1111x over previous
#include <cuda_runtime.h>
#include <cuda_bf16.h>
#include <math.h>

#define NN 50000
#define NE 800000
#define HD 256
#define NG 64
#define SCAN_BLKS 196   // ceil(50000/256)

// ---------------- scratch (device globals; no runtime allocation) ----------------
__device__ __align__(16) float g_h [(size_t)NN*HD];
__device__ __align__(16) float g_r [(size_t)NN*HD];
__device__ __align__(16) float g_xp[(size_t)NN*HD];
__device__ float g_dinv[NN];
__device__ int   g_cnt[NN];
__device__ int   g_incl[NN];
__device__ int   g_rowptr[NN+1];
__device__ int   g_cursor[NN];
__device__ __align__(16) int2 g_edge[NE];
__device__ int   g_bsum[SCAN_BLKS];
__device__ int   g_bscan[SCAN_BLKS];
__device__ __align__(16) float g_stat0[HD];      // input BN stats
__device__ __align__(16) float g_stat1[HD];
__device__ __align__(16) float g_ls0[3*HD];      // per-layer hidden BN stats
__device__ __align__(16) float g_ls1[3*HD];
// pre-packed bf16x2 weights TRANSPOSED: [N][K/2] u32; hi and mid parts
__device__ __align__(16) unsigned g_W0h[HD*HD/2], g_W0m[HD*HD/2];
__device__ __align__(16) unsigned g_W1h[HD*HD/2], g_W1m[HD*HD/2];
__device__ __align__(16) unsigned g_W2h[HD*HD/2], g_W2m[HD*HD/2];
__device__ __align__(16) unsigned g_Wa1h[128*HD/2], g_Wa1m[128*HD/2];
__device__ __align__(16) float g_cb[HD];
__device__ float g_score[NN];
__device__ float g_pm[SCAN_BLKS], g_ps[SCAN_BLKS];
__device__ float g_soft[2];
__device__ __align__(16) float g_pooled[NG*HD];
__device__ float g_cntf[NG];

// ---------------- helpers ----------------
__device__ __forceinline__ unsigned pack_bf16(float lo, float hi) {
    unsigned r;
    asm("cvt.rn.bf16x2.f32 %0, %1, %2;" : "=r"(r) : "f"(hi), "f"(lo));
    return r;
}
__device__ __forceinline__ float bf16rt(float x) {
    __nv_bfloat16 b = __float2bfloat16_rn(x);
    return __bfloat162float(b);
}
__device__ __forceinline__ void mma_bf16(float* c,
    unsigned a0, unsigned a1, unsigned a2, unsigned a3,
    unsigned b0, unsigned b1)
{
    asm volatile(
        "mma.sync.aligned.m16n8k16.row.col.f32.bf16.bf16.f32 "
        "{%0,%1,%2,%3},{%4,%5,%6,%7},{%8,%9},{%0,%1,%2,%3};\n"
        : "+f"(c[0]), "+f"(c[1]), "+f"(c[2]), "+f"(c[3])
        : "r"(a0), "r"(a1), "r"(a2), "r"(a3), "r"(b0), "r"(b1));
}
__device__ __forceinline__ void ldsm4(unsigned* r, const void* p) {
    unsigned a = (unsigned)__cvta_generic_to_shared(p);
    asm volatile("ldmatrix.sync.aligned.m8n8.x4.shared.b16 {%0,%1,%2,%3}, [%4];"
        : "=r"(r[0]), "=r"(r[1]), "=r"(r[2]), "=r"(r[3]) : "r"(a));
}
__device__ __forceinline__ unsigned sw128(unsigned b) { return b ^ ((b >> 3) & 0x70u); }
__device__ __forceinline__ void cpa16(unsigned dst, const void* src) {
    asm volatile("cp.async.cg.shared.global [%0], [%1], 16;"
        :: "r"(dst), "l"(src) : "memory");
}

// ---------------- input BN stats + degree histogram (merged) ----------------
// blocks [0,512): column stats over x. blocks [512,1536): degree atomics over dst.
__global__ void stats_deg(const float* __restrict__ x, const int* __restrict__ dst) {
    int b = blockIdx.x;
    if (b < 512) {
        int t = threadIdx.x;
        float s = 0.f, q = 0.f;
        for (int r = b; r < NN; r += 512) {
            float v = x[(size_t)r*HD + t];
            s += v; q += v*v;
        }
        atomicAdd(&g_stat0[t], s);
        atomicAdd(&g_stat1[t], q);
    } else {
        int base = (b - 512)*256 + threadIdx.x;
        for (int e = base; e < NE; e += 1024*256)
            atomicAdd(&g_cnt[dst[e]], 1);
    }
}

// Fold input BN into W0 (transposed packed bf16x2 hi/mid) + folded bias cb.
__global__ void fold0(const float* __restrict__ W0, const float* __restrict__ bing,
                      const float* __restrict__ binb) {
    int j = threadIdx.x;
    int k2 = blockIdx.x;
    if (k2 < HD/2) {
        int k0 = 2*k2, k1 = 2*k2+1;
        float m0 = g_stat0[k0]*(1.f/NN), m1 = g_stat0[k1]*(1.f/NN);
        float a0 = rsqrtf(g_stat1[k0]*(1.f/NN) - m0*m0 + 1e-5f) * bing[k0];
        float a1 = rsqrtf(g_stat1[k1]*(1.f/NN) - m1*m1 + 1e-5f) * bing[k1];
        float v0 = a0 * W0[k0*HD + j];
        float v1 = a1 * W0[k1*HD + j];
        float h0 = bf16rt(v0), h1 = bf16rt(v1);
        g_W0h[j*(HD/2) + k2] = pack_bf16(h0, h1);
        g_W0m[j*(HD/2) + k2] = pack_bf16(v0 - h0, v1 - h1);
    } else {
        __shared__ float scin[HD];
        float m = g_stat0[j]*(1.f/NN);
        float rs = rsqrtf(g_stat1[j]*(1.f/NN) - m*m + 1e-5f);
        scin[j] = binb[j] - m * rs * bing[j];
        __syncthreads();
        float s = 0.f;
        for (int kk = 0; kk < HD; kk++) s += scin[kk] * W0[kk*HD + j];
        g_cb[j] = s;
    }
}

// all three remaining weights -> transposed packed bf16x2 hi/mid, one launch
__global__ void presplit_all(const float* __restrict__ W1, const float* __restrict__ W2,
                             const float* __restrict__ Wa1) {
    int idx = blockIdx.x*256 + threadIdx.x;
    const float* src; unsigned *dh, *dm; int Nn, local;
    if (idx < 32768)      { src = W1;  dh = g_W1h;  dm = g_W1m;  Nn = 256; local = idx; }
    else if (idx < 65536) { src = W2;  dh = g_W2h;  dm = g_W2m;  Nn = 256; local = idx - 32768; }
    else if (idx < 81920) { src = Wa1; dh = g_Wa1h; dm = g_Wa1m; Nn = 128; local = idx - 65536; }
    else return;
    int n = local >> 7, k2 = local & 127;
    float v0 = src[(2*k2)*Nn + n];
    float v1 = src[(2*k2+1)*Nn + n];
    float h0 = bf16rt(v0), h1 = bf16rt(v1);
    dh[local] = pack_bf16(h0, h1);
    dm[local] = pack_bf16(v0 - h0, v1 - h1);
}

// ---------------- CSR build ----------------
__global__ void scan1() {
    __shared__ int sm[256];
    int t = threadIdx.x;
    int i = blockIdx.x*256 + t;
    int v = (i < NN) ? g_cnt[i] : 0;
    if (i < NN) g_dinv[i] = rsqrtf((float)v + 1.f);
    sm[t] = v; __syncthreads();
    for (int off = 1; off < 256; off <<= 1) {
        int tv = (t >= off) ? sm[t-off] : 0;
        __syncthreads();
        sm[t] += tv;
        __syncthreads();
    }
    if (i < NN) g_incl[i] = sm[t];
    if (t == 255) g_bsum[blockIdx.x] = sm[255];
}
__global__ void scan2() {
    __shared__ int sm[256];
    int t = threadIdx.x;
    sm[t] = (t < SCAN_BLKS) ? g_bsum[t] : 0; __syncthreads();
    for (int off = 1; off < 256; off <<= 1) {
        int tv = (t >= off) ? sm[t-off] : 0;
        __syncthreads();
        sm[t] += tv;
        __syncthreads();
    }
    if (t < SCAN_BLKS) g_bscan[t] = sm[t];
}
__global__ void scan3() {
    int t = threadIdx.x;
    int i = blockIdx.x*256 + t;
    if (i < NN) {
        int off = (blockIdx.x > 0) ? g_bscan[blockIdx.x-1] : 0;
        int ex = off + g_incl[i] - g_cnt[i];
        g_rowptr[i] = ex;
        g_cursor[i] = ex;
        g_cnt[i] = 0;
    }
    if (i == 0) g_rowptr[NN] = NE;
}
__global__ void fill_kernel(const int* __restrict__ src, const int* __restrict__ dst) {
    for (int e = blockIdx.x*blockDim.x + threadIdx.x; e < NE; e += gridDim.x*blockDim.x) {
        int d = dst[e];
        int s = src[e];
        int p = atomicAdd(&g_cursor[d], 1);
        float cf = g_dinv[s] * g_dinv[d];
        g_edge[p] = make_int2(s, __float_as_int(cf));
    }
}

// ---------------- 3xBF16 tensor-core GEMM (ldmatrix + SW128 + cp.async B) ----------------
__global__ __launch_bounds__(256, 2) void bf16_gemm(
    const float* __restrict__ A, const unsigned* __restrict__ Bth,
    const unsigned* __restrict__ Btm,
    const float* __restrict__ bias, float* __restrict__ C, int M, int Nn,
    const float* __restrict__ Wa2, const float* __restrict__ ba2,
    float* __restrict__ score)
{
    __shared__ __align__(16) unsigned char smAh[2][4096], smAm[2][4096];
    __shared__ __align__(16) unsigned char smBh[2][4096], smBm[2][4096];
    __shared__ float srow[128];

    int tid = threadIdx.x;
    int bm = blockIdx.x*128, bn = blockIdx.y*128;
    int lane = tid & 31, w = tid >> 5;
    int wm = (w >> 2) * 64, wn = (w & 3) * 32;
    int lr = lane & 15, lh = lane >> 4;
    int lrow = lane >> 2, tg = lane & 3;

    int arow = tid & 127, aks = tid >> 7;
    int brow = tid >> 1,  bks = tid & 1;

    unsigned asw = sw128((unsigned)(arow*32 + aks*16));
    unsigned bsw = sw128((unsigned)(brow*32 + bks*16));
    unsigned sbh0 = (unsigned)__cvta_generic_to_shared(&smBh[0][0]);
    unsigned sbm0 = (unsigned)__cvta_generic_to_shared(&smBm[0][0]);
    const char* bSrcH = (const char*)Bth + ((size_t)(bn+brow)*128 + bks*4) * 4;
    const char* bSrcM = (const char*)Btm + ((size_t)(bn+brow)*128 + bks*4) * 4;

    float4 ra0, ra1;

    float acc[4][4][4];
    #pragma unroll
    for (int a = 0; a < 4; a++)
        #pragma unroll
        for (int b = 0; b < 4; b++)
            #pragma unroll
            for (int cc = 0; cc < 4; cc++) acc[a][b][cc] = 0.f;

    auto LOADA = [&](int kt) {
        const float* ap = A + (size_t)(bm+arow)*256 + kt*16 + aks*8;
        if (bm + arow < M) { ra0 = *(const float4*)ap; ra1 = *(const float4*)(ap+4); }
        else { ra0 = make_float4(0.f,0.f,0.f,0.f); ra1 = ra0; }
    };
    auto CPB = [&](int kt, int buf) {
        size_t ko = (size_t)kt*32;
        cpa16(sbh0 + buf*4096 + bsw, bSrcH + ko);
        cpa16(sbm0 + buf*4096 + bsw, bSrcM + ko);
        asm volatile("cp.async.commit_group;" ::: "memory");
    };
    auto STOREA = [&](int buf) {
        float v[8] = {ra0.x, ra0.y, ra0.z, ra0.w, ra1.x, ra1.y, ra1.z, ra1.w};
        unsigned hp[4], mp[4];
        #pragma unroll
        for (int j = 0; j < 4; j++) {
            float e = v[2*j], o = v[2*j+1];
            float eh = bf16rt(e), oh = bf16rt(o);
            hp[j] = pack_bf16(eh, oh);
            mp[j] = pack_bf16(e - eh, o - oh);
        }
        *(uint4*)&smAh[buf][asw] = make_uint4(hp[0], hp[1], hp[2], hp[3]);
        *(uint4*)&smAm[buf][asw] = make_uint4(mp[0], mp[1], mp[2], mp[3]);
    };

    if (score && tid < 128) srow[tid] = 0.f;

    LOADA(0); CPB(0, 0); STOREA(0);
    asm volatile("cp.async.wait_group 0;" ::: "memory");
    __syncthreads();

    for (int kt = 0; kt < 16; kt++) {
        int buf = kt & 1;
        if (kt < 15) { LOADA(kt+1); CPB(kt+1, buf ^ 1); }

        unsigned ah[4][4], am[4][4], bh[2][4], bmm[2][4];
        #pragma unroll
        for (int mt = 0; mt < 4; mt++) {
            unsigned byte = sw128((unsigned)((wm + mt*16 + lr)*32 + lh*16));
            ldsm4(ah[mt], &smAh[buf][byte]);
            ldsm4(am[mt], &smAm[buf][byte]);
        }
        #pragma unroll
        for (int np = 0; np < 2; np++) {
            unsigned byte = sw128((unsigned)((wn + np*16 + lr)*32 + lh*16));
            ldsm4(bh[np],  &smBh[buf][byte]);
            ldsm4(bmm[np], &smBm[buf][byte]);
        }
        #pragma unroll
        for (int nt = 0; nt < 4; nt++) {
            int np = nt >> 1, sel = nt & 1;
            unsigned b0h = bh[np][sel],  b1h = bh[np][sel+2];
            unsigned b0m = bmm[np][sel], b1m = bmm[np][sel+2];
            #pragma unroll
            for (int mt = 0; mt < 4; mt++) {
                mma_bf16(acc[mt][nt], ah[mt][0],ah[mt][1],ah[mt][2],ah[mt][3], b0h, b1h);
                mma_bf16(acc[mt][nt], am[mt][0],am[mt][1],am[mt][2],am[mt][3], b0h, b1h);
                mma_bf16(acc[mt][nt], ah[mt][0],ah[mt][1],ah[mt][2],ah[mt][3], b0m, b1m);
            }
        }
        if (kt < 15) {
            STOREA(buf ^ 1);
            asm volatile("cp.async.wait_group 0;" ::: "memory");
            __syncthreads();
        }
    }

    if (score) {
        __syncthreads();
        #pragma unroll
        for (int mt = 0; mt < 4; mt++) {
            float p0 = 0.f, p1 = 0.f;
            #pragma unroll
            for (int nt = 0; nt < 4; nt++) {
                int cidx = wn + nt*8 + 2*tg;
                float bv0 = bias[cidx], bv1 = bias[cidx+1];
                float w0 = Wa2[cidx],  w1 = Wa2[cidx+1];
                float v;
                v = acc[mt][nt][0] + bv0; v = (v > 0.f) ? v : 0.01f*v; p0 = fmaf(v, w0, p0);
                v = acc[mt][nt][1] + bv1; v = (v > 0.f) ? v : 0.01f*v; p0 = fmaf(v, w1, p0);
                v = acc[mt][nt][2] + bv0; v = (v > 0.f) ? v : 0.01f*v; p1 = fmaf(v, w0, p1);
                v = acc[mt][nt][3] + bv1; v = (v > 0.f) ? v : 0.01f*v; p1 = fmaf(v, w1, p1);
            }
            int rl = wm + mt*16 + lrow;
            atomicAdd(&srow[rl],     p0);
            atomicAdd(&srow[rl + 8], p1);
        }
        __syncthreads();
        if (tid < 128 && bm + tid < M) score[bm + tid] = srow[tid] + ba2[0];
        return;
    }

    #pragma unroll
    for (int nt = 0; nt < 4; nt++) {
        int cidx = bn + wn + nt*8 + 2*tg;
        float b0v = bias ? bias[cidx]   : 0.f;
        float b1v = bias ? bias[cidx+1] : 0.f;
        #pragma unroll
        for (int mt = 0; mt < 4; mt++) {
            int r0 = bm + wm + mt*16 + lrow;
            if (r0 < M)
                *(float2*)(C + (size_t)r0*Nn + cidx) =
                    make_float2(acc[mt][nt][0]+b0v, acc[mt][nt][1]+b1v);
            if (r0 + 8 < M)
                *(float2*)(C + (size_t)(r0+8)*Nn + cidx) =
                    make_float2(acc[mt][nt][2]+b0v, acc[mt][nt][3]+b1v);
        }
    }
}

// ---------------- aggregation + bias + relu + per-layer BN-stat partials (R13-proven) ----
__global__ __launch_bounds__(256) void agg_kernel(const float* __restrict__ bias, int layer) {
    int c = (threadIdx.x & 127) * 2;
    int half = threadIdx.x >> 7;
    int row0 = blockIdx.x * 32 + half * 16;
    float2 bia = *(const float2*)&bias[c];
    float ssx=0.f, ssy=0.f, qqx=0.f, qqy=0.f;
    for (int r = 0; r < 16; r++) {
        int i = row0 + r;
        if (i >= NN) break;
        float di = g_dinv[i];
        float2 hv = *(const float2*)&g_h[(size_t)i*HD + c];
        float ax = hv.x * di * di, ay = hv.y * di * di;
        int p = g_rowptr[i], e = g_rowptr[i+1];
        for (; p + 8 <= e; p += 8) {
            int2 e0 = g_edge[p],   e1 = g_edge[p+1];
            int2 e2 = g_edge[p+2], e3 = g_edge[p+3];
            int2 e4 = g_edge[p+4], e5 = g_edge[p+5];
            int2 e6 = g_edge[p+6], e7 = g_edge[p+7];
            float2 v0 = *(const float2*)&g_h[(size_t)e0.x*HD + c];
            float2 v1 = *(const float2*)&g_h[(size_t)e1.x*HD + c];
            float2 v2 = *(const float2*)&g_h[(size_t)e2.x*HD + c];
            float2 v3 = *(const float2*)&g_h[(size_t)e3.x*HD + c];
            float2 v4 = *(const float2*)&g_h[(size_t)e4.x*HD + c];
            float2 v5 = *(const float2*)&g_h[(size_t)e5.x*HD + c];
            float2 v6 = *(const float2*)&g_h[(size_t)e6.x*HD + c];
            float2 v7 = *(const float2*)&g_h[(size_t)e7.x*HD + c];
            float f0 = __int_as_float(e0.y), f1 = __int_as_float(e1.y);
            float f2 = __int_as_float(e2.y), f3 = __int_as_float(e3.y);
            float f4 = __int_as_float(e4.y), f5 = __int_as_float(e5.y);
            float f6 = __int_as_float(e6.y), f7 = __int_as_float(e7.y);
            ax = fmaf(v0.x, f0, ax); ay = fmaf(v0.y, f0, ay);
            ax = fmaf(v1.x, f1, ax); ay = fmaf(v1.y, f1, ay);
            ax = fmaf(v2.x, f2, ax); ay = fmaf(v2.y, f2, ay);
            ax = fmaf(v3.x, f3, ax); ay = fmaf(v3.y, f3, ay);
            ax = fmaf(v4.x, f4, ax); ay = fmaf(v4.y, f4, ay);
            ax = fmaf(v5.x, f5, ax); ay = fmaf(v5.y, f5, ay);
            ax = fmaf(v6.x, f6, ax); ay = fmaf(v6.y, f6, ay);
            ax = fmaf(v7.x, f7, ax); ay = fmaf(v7.y, f7, ay);
        }
        for (; p < e; p++) {
            int2 ed = g_edge[p];
            float2 vv = *(const float2*)&g_h[(size_t)ed.x*HD + c];
            float ff = __int_as_float(ed.y);
            ax = fmaf(vv.x, ff, ax); ay = fmaf(vv.y, ff, ay);
        }
        float vx = fmaxf(ax + bia.x, 0.f);
        float vy = fmaxf(ay + bia.y, 0.f);
        *(float2*)&g_r[(size_t)i*HD + c] = make_float2(vx, vy);
        ssx += vx; ssy += vy; qqx += vx*vx; qqy += vy*vy;
    }
    atomicAdd(&g_ls0[layer*HD + c],   ssx);
    atomicAdd(&g_ls0[layer*HD + c+1], ssy);
    atomicAdd(&g_ls1[layer*HD + c],   qqx);
    atomicAdd(&g_ls1[layer*HD + c+1], qqy);
}

// xp = bn(r) (+ xp if residual); A/C computed per block from per-layer stats
__global__ void bnnorm_kernel(int residual, int layer,
                              const float* __restrict__ g, const float* __restrict__ b) {
    __shared__ float sA[HD], sC[HD];
    int t = threadIdx.x;
    {
        float m = g_ls0[layer*HD + t] * (1.f/NN);
        float v = g_ls1[layer*HD + t] * (1.f/NN) - m*m;
        float rs = rsqrtf(v + 1e-5f);
        sA[t] = rs * g[t];
        sC[t] = b[t] - m * rs * g[t];
    }
    __syncthreads();
    int idx = blockIdx.x*256 + t;
    if (idx >= NN*HD/4) return;
    int c4 = idx & 63;
    float4 v = ((const float4*)g_r)[idx];
    float4 A = *(const float4*)&sA[c4*4];
    float4 C = *(const float4*)&sC[c4*4];
    float4 o = make_float4(v.x*A.x+C.x, v.y*A.y+C.y, v.z*A.z+C.z, v.w*A.w+C.w);
    if (residual) {
        float4 p = ((const float4*)g_xp)[idx];
        o.x += p.x; o.y += p.y; o.z += p.z; o.w += p.w;
    }
    ((float4*)g_xp)[idx] = o;
}

// ---------------- softmax over all N (+ per-group count histogram) ----------------
__global__ void smax_part(const int* __restrict__ batch) {
    __shared__ float sm[256], ss[256];
    __shared__ int hist[NG];
    int t = threadIdx.x;
    if (t < NG) hist[t] = 0;
    float m = -3.4e38f, s = 0.f;
    for (int i = blockIdx.x*256 + t; i < NN; i += SCAN_BLKS*256) {
        float v = g_score[i];
        float nm = fmaxf(m, v);
        float ns = expf(v - nm);
        if (s > 0.f) ns += s * expf(m - nm);
        s = ns; m = nm;
        atomicAdd(&hist[batch[i]], 1);
    }
    sm[t] = m; ss[t] = s; __syncthreads();
    for (int off = 128; off; off >>= 1) {
        if (t < off) {
            float m2 = sm[t+off], s2 = ss[t+off];
            float nm = fmaxf(sm[t], m2);
            float acc = 0.f;
            if (ss[t] > 0.f) acc += ss[t] * expf(sm[t] - nm);
            if (s2    > 0.f) acc += s2    * expf(m2    - nm);
            sm[t] = nm; ss[t] = acc;
        }
        __syncthreads();
    }
    if (t == 0) { g_pm[blockIdx.x] = sm[0]; g_ps[blockIdx.x] = ss[0]; }
    if (t < NG && hist[t]) atomicAdd(&g_cntf[t], (float)hist[t]);
}
__global__ void smax_final() {
    __shared__ float sm[256], ss[256];
    int t = threadIdx.x;
    sm[t] = (t < SCAN_BLKS) ? g_pm[t] : -3.4e38f;
    ss[t] = (t < SCAN_BLKS) ? g_ps[t] : 0.f;
    __syncthreads();
    for (int off = 128; off; off >>= 1) {
        if (t < off) {
            float m2 = sm[t+off], s2 = ss[t+off];
            float nm = fmaxf(sm[t], m2);
            float acc = 0.f;
            if (ss[t] > 0.f) acc += ss[t] * expf(sm[t] - nm);
            if (s2    > 0.f) acc += s2    * expf(m2    - nm);
            sm[t] = nm; ss[t] = acc;
        }
        __syncthreads();
    }
    if (t == 0) { g_soft[0] = sm[0]; g_soft[1] = 1.f / ss[0]; }
}

// pooled[g] += sum xp[i]*w[i], w computed inline from score; float2 columns.
__global__ __launch_bounds__(256) void pool_kernel(const int* __restrict__ batch) {
    int c = (threadIdx.x & 127) * 2;
    int half = threadIdx.x >> 7;
    int row0 = blockIdx.x * 128 + half * 64;
    if (row0 >= NN) return;
    float smax = g_soft[0], sinv = g_soft[1];
    float ax = 0.f, ay = 0.f;
    int cur = batch[row0];
    for (int r = 0; r < 64; r++) {
        int i = row0 + r;
        if (i >= NN) break;
        int g = batch[i];
        if (g != cur) {
            if (ax != 0.f || ay != 0.f) {
                atomicAdd(&g_pooled[cur*HD + c],   ax);
                atomicAdd(&g_pooled[cur*HD + c+1], ay);
            }
            ax = 0.f; ay = 0.f; cur = g;
        }
        float wv = expf(g_score[i] - smax) * sinv;
        float2 v = *(const float2*)&g_xp[(size_t)i*HD + c];
        ax = fmaf(v.x, wv, ax);
        ay = fmaf(v.y, wv, ay);
    }
    atomicAdd(&g_pooled[cur*HD + c],   ax);
    atomicAdd(&g_pooled[cur*HD + c+1], ay);
}

// out + reset of all replay-accumulated state
__global__ void final_kernel(const float* __restrict__ Wo, const float* __restrict__ bo,
                             float* __restrict__ out) {
    int t = threadIdx.x;
    float s = 0.f;
    int g = t >> 1, o = t & 1;
    if (t < NG*2) {
        for (int h = 0; h < HD; h++) s = fmaf(g_pooled[g*HD + h], Wo[h*2 + o], s);
        s = s / fmaxf(g_cntf[g], 1.f) + bo[o];
    }
    __syncthreads();
    if (t < NG*2) out[t] = s;
    for (int i = t; i < NG*HD; i += 128) g_pooled[i] = 0.f;
    if (t < NG) g_cntf[t] = 0.f;
    for (int i = t; i < 3*HD; i += 128) { g_ls0[i] = 0.f; g_ls1[i] = 0.f; }
    for (int i = t; i < HD; i += 128) { g_stat0[i] = 0.f; g_stat1[i] = 0.f; }
}

// ---------------- launch ----------------
extern "C" void kernel_launch(void* const* d_in, const int* in_sizes, int n_in,
                              void* d_out, int out_size) {
    const float* x      = (const float*)d_in[0];
    const int*   ei     = (const int*)d_in[1];
    const int*   src    = ei;
    const int*   dst    = ei + NE;
    const int*   batch  = (const int*)d_in[2];
    const float* bing   = (const float*)d_in[3];
    const float* binb   = (const float*)d_in[4];
    const float* W[3]   = {(const float*)d_in[5],  (const float*)d_in[9],  (const float*)d_in[13]};
    const float* bL[3]  = {(const float*)d_in[6],  (const float*)d_in[10], (const float*)d_in[14]};
    const float* bng[3] = {(const float*)d_in[7],  (const float*)d_in[11], (const float*)d_in[15]};
    const float* bnb[3] = {(const float*)d_in[8],  (const float*)d_in[12], (const float*)d_in[16]};
    const float* Wa1    = (const float*)d_in[17];
    const float* ba1    = (const float*)d_in[18];
    const float* Wa2    = (const float*)d_in[19];
    const float* ba2    = (const float*)d_in[20];
    const float* Wo     = (const float*)d_in[21];
    const float* bo     = (const float*)d_in[22];
    float* out = (float*)d_out;

    void* p;
    cudaGetSymbolAddress(&p, g_h);     float* ph   = (float*)p;
    cudaGetSymbolAddress(&p, g_xp);    float* pxp  = (float*)p;
    cudaGetSymbolAddress(&p, g_score); float* psc  = (float*)p;
    cudaGetSymbolAddress(&p, g_W0h);  unsigned* pw0h = (unsigned*)p;
    cudaGetSymbolAddress(&p, g_W0m);  unsigned* pw0m = (unsigned*)p;
    cudaGetSymbolAddress(&p, g_W1h);  unsigned* pw1h = (unsigned*)p;
    cudaGetSymbolAddress(&p, g_W1m);  unsigned* pw1m = (unsigned*)p;
    cudaGetSymbolAddress(&p, g_W2h);  unsigned* pw2h = (unsigned*)p;
    cudaGetSymbolAddress(&p, g_W2m);  unsigned* pw2m = (unsigned*)p;
    cudaGetSymbolAddress(&p, g_Wa1h); unsigned* pwah = (unsigned*)p;
    cudaGetSymbolAddress(&p, g_Wa1m); unsigned* pwam = (unsigned*)p;
    cudaGetSymbolAddress(&p, g_cb);   float* pcb  = (float*)p;

    dim3 gemm_grid((NN+127)/128, 2);
    dim3 attn_grid((NN+127)/128, 1);
    int agg_blocks = (NN+31)/32;
    int bn_blocks = (NN*HD/4 + 255)/256;

    stats_deg<<<1536,256>>>(x, dst);
    fold0<<<HD/2+1,HD>>>(W[0], bing, binb);
    presplit_all<<<320,256>>>(W[1], W[2], Wa1);
    bf16_gemm<<<gemm_grid,256>>>(x, pw0h, pw0m, pcb, ph, NN, HD,
                                 nullptr, nullptr, nullptr);        // <- profiled (4th launch)

    // CSR build (independent of GEMM result)
    scan1<<<SCAN_BLKS,256>>>();
    scan2<<<1,256>>>();
    scan3<<<SCAN_BLKS,256>>>();
    fill_kernel<<<1024,256>>>(src, dst);

    // layer 0
    agg_kernel<<<agg_blocks,256>>>(bL[0], 0);
    bnnorm_kernel<<<bn_blocks,256>>>(0, 0, bng[0], bnb[0]);

    // layers 1,2 with residual
    unsigned* pwsh[3] = {pw0h, pw1h, pw2h};
    unsigned* pwsm[3] = {pw0m, pw1m, pw2m};
    for (int l = 1; l < 3; l++) {
        bf16_gemm<<<gemm_grid,256>>>(pxp, pwsh[l], pwsm[l], nullptr, ph, NN, HD,
                                     nullptr, nullptr, nullptr);
        agg_kernel<<<agg_blocks,256>>>(bL[l], l);
        bnnorm_kernel<<<bn_blocks,256>>>(1, l, bng[l], bnb[l]);
    }

    // attention: GEMM with fused lrelu·Wa2 score epilogue
    bf16_gemm<<<attn_grid,256>>>(pxp, pwah, pwam, ba1, nullptr, NN, 128,
                                 Wa2, ba2, psc);
    smax_part<<<SCAN_BLKS,256>>>(batch);
    smax_final<<<1,256>>>();
    pool_kernel<<<(NN+127)/128,256>>>(batch);
    final_kernel<<<1,128>>>(Wo, bo, out);
}